// round 2
// baseline (speedup 1.0000x reference)
#include <cuda_runtime.h>
#include <cuda_fp16.h>
#include <mma.h>

using namespace nvcuda;

// Problem dims (fixed by dataset)
#define M_DIM 4096
#define K_DIM 4096
#define N_DIM 11008
#define NPACK (N_DIM / 8)   // 1376
#define GROUP 128

// Static scratch (allowed; no cudaMalloc). 90.2 MB W + 32 MB X.
__device__ __half g_W[(size_t)K_DIM * N_DIM];   // dequantized weights [K, N] fp16
__device__ __half g_X[(size_t)M_DIM * K_DIM];   // activations [M, K] fp16

// ---------------------------------------------------------------------------
// Kernel 0: convert x (float32 from harness, fp16-exact values) -> fp16.
// 8 floats per thread, fully vectorized.
// ---------------------------------------------------------------------------
__global__ void __launch_bounds__(256) convert_x_kernel(const float* __restrict__ x)
{
    size_t i = ((size_t)blockIdx.x * 256 + threadIdx.x) * 8;
    float4 v0 = *reinterpret_cast<const float4*>(x + i);
    float4 v1 = *reinterpret_cast<const float4*>(x + i + 4);
    __half2 o[4];
    o[0] = __floats2half2_rn(v0.x, v0.y);
    o[1] = __floats2half2_rn(v0.z, v0.w);
    o[2] = __floats2half2_rn(v1.x, v1.y);
    o[3] = __floats2half2_rn(v1.z, v1.w);
    *reinterpret_cast<uint4*>(&g_X[i]) = *reinterpret_cast<const uint4*>(o);
}

// ---------------------------------------------------------------------------
// Kernel 1: AWQ int4 dequant. One thread per packed int32 (8 output halves).
// AWQ order map [0,2,4,6,1,3,5,7] -> logical-column shifts {0,16,4,20,8,24,12,28}.
// scales are float32 on device (fp16-exact values): f32 multiply + single
// rounding to fp16 == reference's fp16 dequant.
// ---------------------------------------------------------------------------
__global__ void __launch_bounds__(256) dequant_kernel(
    const int* __restrict__ qweight,
    const int* __restrict__ qzeros,
    const float* __restrict__ scales)
{
    int idx = blockIdx.x * 256 + threadIdx.x;
    if (idx >= K_DIM * NPACK) return;
    int k = idx / NPACK;
    int c = idx - k * NPACK;
    int g = k >> 7;  // k / GROUP

    unsigned q = (unsigned)qweight[idx];
    unsigned z = (unsigned)qzeros[g * NPACK + c];

    float4 s0 = *reinterpret_cast<const float4*>(scales + (size_t)g * N_DIM + (size_t)c * 8);
    float4 s1 = *reinterpret_cast<const float4*>(scales + (size_t)g * N_DIM + (size_t)c * 8 + 4);
    float sf[8] = {s0.x, s0.y, s0.z, s0.w, s1.x, s1.y, s1.z, s1.w};

    const int shifts[8] = {0, 16, 4, 20, 8, 24, 12, 28};
    __half2 out[4];
#pragma unroll
    for (int j = 0; j < 4; ++j) {
        int i0 = (int)((q >> shifts[2 * j]) & 0xF) - (int)((z >> shifts[2 * j]) & 0xF);
        int i1 = (int)((q >> shifts[2 * j + 1]) & 0xF) - (int)((z >> shifts[2 * j + 1]) & 0xF);
        out[j] = __floats2half2_rn((float)i0 * sf[2 * j], (float)i1 * sf[2 * j + 1]);
    }
    *reinterpret_cast<uint4*>(&g_W[(size_t)k * N_DIM + (size_t)c * 8]) =
        *reinterpret_cast<const uint4*>(out);
}

// ---------------------------------------------------------------------------
// Kernel 2: fp16 GEMM, fp32 accumulation via wmma, fused bias epilogue.
// Block tile 128x128, K-step 32, 8 warps (2x4), each warp 64x32 (4x2 frags).
// Output float32 = widen( round_fp16(acc) + bias_fp16 ) to match reference
// fp16 rounding behavior.
// ---------------------------------------------------------------------------
constexpr int BM = 128;
constexpr int BN = 128;
constexpr int BK = 32;
constexpr int A_LD = BK + 8;    // 40
constexpr int B_LD = BN + 8;    // 136
constexpr int SMEM_BYTES = 128 * 128 * 4;  // 64 KB (fp32 C stage dominates)

extern __shared__ char smem_raw[];

__global__ void __launch_bounds__(256) gemm_kernel(
    const float* __restrict__ bias,
    float* __restrict__ out)
{
    __half* As = reinterpret_cast<__half*>(smem_raw);   // [128][40]
    __half* Bs = As + BM * A_LD;                        // [32][136]

    const int tid  = threadIdx.x;
    const int warp = tid >> 5;
    const int wrow = warp >> 2;   // 0..1
    const int wcol = warp & 3;    // 0..3
    const int m0 = blockIdx.y * BM;
    const int n0 = blockIdx.x * BN;

    wmma::fragment<wmma::accumulator, 16, 16, 16, float> acc[4][2];
#pragma unroll
    for (int i = 0; i < 4; ++i)
#pragma unroll
        for (int j = 0; j < 2; ++j)
            wmma::fill_fragment(acc[i][j], 0.0f);

    const int arow = tid >> 1;
    const int acol = (tid & 1) * 16;
    const int brow = tid >> 4;
    const int bcol = (tid & 15) * 8;

    const __half* xg = g_X + (size_t)(m0 + arow) * K_DIM + acol;

    for (int kt = 0; kt < K_DIM; kt += BK) {
        uint4 av0 = *reinterpret_cast<const uint4*>(xg + kt);
        uint4 av1 = *reinterpret_cast<const uint4*>(xg + kt + 8);
        const __half* wg0 = g_W + (size_t)(kt + brow) * N_DIM + n0 + bcol;
        const __half* wg1 = g_W + (size_t)(kt + brow + 16) * N_DIM + n0 + bcol;
        uint4 bv0 = *reinterpret_cast<const uint4*>(wg0);
        uint4 bv1 = *reinterpret_cast<const uint4*>(wg1);

        __syncthreads();
        *reinterpret_cast<uint4*>(&As[arow * A_LD + acol])        = av0;
        *reinterpret_cast<uint4*>(&As[arow * A_LD + acol + 8])    = av1;
        *reinterpret_cast<uint4*>(&Bs[brow * B_LD + bcol])        = bv0;
        *reinterpret_cast<uint4*>(&Bs[(brow + 16) * B_LD + bcol]) = bv1;
        __syncthreads();

#pragma unroll
        for (int kk = 0; kk < BK; kk += 16) {
            wmma::fragment<wmma::matrix_a, 16, 16, 16, __half, wmma::row_major> af[4];
            wmma::fragment<wmma::matrix_b, 16, 16, 16, __half, wmma::row_major> bf[2];
#pragma unroll
            for (int i = 0; i < 4; ++i)
                wmma::load_matrix_sync(af[i], &As[(wrow * 64 + i * 16) * A_LD + kk], A_LD);
#pragma unroll
            for (int j = 0; j < 2; ++j)
                wmma::load_matrix_sync(bf[j], &Bs[kk * B_LD + wcol * 32 + j * 16], B_LD);
#pragma unroll
            for (int i = 0; i < 4; ++i)
#pragma unroll
                for (int j = 0; j < 2; ++j)
                    wmma::mma_sync(acc[i][j], af[i], bf[j], acc[i][j]);
        }
    }

    // Epilogue: stage fp32 C in shared, round to fp16, add fp16 bias, widen.
    __syncthreads();
    float* Cs = reinterpret_cast<float*>(smem_raw);  // [128][128]
#pragma unroll
    for (int i = 0; i < 4; ++i)
#pragma unroll
        for (int j = 0; j < 2; ++j)
            wmma::store_matrix_sync(&Cs[(wrow * 64 + i * 16) * 128 + wcol * 32 + j * 16],
                                    acc[i][j], 128, wmma::mem_row_major);
    __syncthreads();

    for (int e = tid; e < (BM * BN) / 4; e += 256) {
        int r = e >> 5;           // 0..127
        int c = (e & 31) * 4;     // 0..124
        float4 v = *reinterpret_cast<const float4*>(&Cs[r * 128 + c]);
        float4 bv = *reinterpret_cast<const float4*>(bias + n0 + c);
        float4 o;
        o.x = __half2float(__hadd(__float2half(v.x), __float2half(bv.x)));
        o.y = __half2float(__hadd(__float2half(v.y), __float2half(bv.y)));
        o.z = __half2float(__hadd(__float2half(v.z), __float2half(bv.z)));
        o.w = __half2float(__hadd(__float2half(v.w), __float2half(bv.w)));
        *reinterpret_cast<float4*>(&out[(size_t)(m0 + r) * N_DIM + n0 + c]) = o;
    }
}

// ---------------------------------------------------------------------------
// Launch: convert -> dequant -> GEMM. Graph-capturable, no allocs, no syncs.
// ---------------------------------------------------------------------------
extern "C" void kernel_launch(void* const* d_in, const int* in_sizes, int n_in,
                              void* d_out, int out_size)
{
    const float* x      = (const float*)d_in[0];
    const int*   qw     = (const int*)d_in[1];
    const int*   qz     = (const int*)d_in[2];
    const float* scales = (const float*)d_in[3];
    const float* bias   = (const float*)d_in[4];
    float*       out    = (float*)d_out;

    cudaFuncSetAttribute(gemm_kernel, cudaFuncAttributeMaxDynamicSharedMemorySize,
                         SMEM_BYTES);

    convert_x_kernel<<<(M_DIM * (size_t)K_DIM) / 8 / 256, 256>>>(x);

    int dq_blocks = (K_DIM * NPACK + 255) / 256;
    dequant_kernel<<<dq_blocks, 256>>>(qw, qz, scales);

    dim3 grid(N_DIM / BN, M_DIM / BM);  // 86 x 32
    gemm_kernel<<<grid, 256, SMEM_BYTES>>>(bias, out);
}

// round 5
// speedup vs baseline: 1.2456x; 1.2456x over previous
#include <cuda_runtime.h>
#include <cuda_fp16.h>
#include <cstdint>

#define M_DIM 4096
#define K_DIM 4096
#define N_DIM 11008
#define NPACK (N_DIM / 8)   // 1376
#define GROUP 128

// Static scratch: W [K, N] fp16 (90.2 MB) + X [M, K] fp16 (32 MB).
__device__ __half g_W[(size_t)K_DIM * N_DIM];
__device__ __half g_X[(size_t)M_DIM * K_DIM];

// ---------------------------------------------------------------------------
// Kernel 0: x f32 -> fp16 (harness promotes fp16 inputs to f32)
// ---------------------------------------------------------------------------
__global__ void __launch_bounds__(256) convert_x_kernel(const float* __restrict__ x)
{
    size_t i = ((size_t)blockIdx.x * 256 + threadIdx.x) * 8;
    float4 v0 = *reinterpret_cast<const float4*>(x + i);
    float4 v1 = *reinterpret_cast<const float4*>(x + i + 4);
    __half2 o[4];
    o[0] = __floats2half2_rn(v0.x, v0.y);
    o[1] = __floats2half2_rn(v0.z, v0.w);
    o[2] = __floats2half2_rn(v1.x, v1.y);
    o[3] = __floats2half2_rn(v1.z, v1.w);
    *reinterpret_cast<uint4*>(&g_X[i]) = *reinterpret_cast<const uint4*>(o);
}

// ---------------------------------------------------------------------------
// Kernel 1: AWQ int4 dequant -> W [K, N] fp16. One thread per packed word.
// AWQ order map [0,2,4,6,1,3,5,7] -> shifts {0,16,4,20,8,24,12,28}.
// ---------------------------------------------------------------------------
__global__ void __launch_bounds__(256) dequant_kernel(
    const int* __restrict__ qweight,
    const int* __restrict__ qzeros,
    const float* __restrict__ scales)
{
    int idx = blockIdx.x * 256 + threadIdx.x;
    if (idx >= K_DIM * NPACK) return;
    int k = idx / NPACK;
    int c = idx - k * NPACK;
    int g = k >> 7;

    unsigned q = (unsigned)qweight[idx];
    unsigned z = (unsigned)qzeros[g * NPACK + c];

    float4 s0 = *reinterpret_cast<const float4*>(scales + (size_t)g * N_DIM + (size_t)c * 8);
    float4 s1 = *reinterpret_cast<const float4*>(scales + (size_t)g * N_DIM + (size_t)c * 8 + 4);
    float sf[8] = {s0.x, s0.y, s0.z, s0.w, s1.x, s1.y, s1.z, s1.w};

    const int shifts[8] = {0, 16, 4, 20, 8, 24, 12, 28};
    __half2 out[4];
#pragma unroll
    for (int j = 0; j < 4; ++j) {
        int i0 = (int)((q >> shifts[2 * j]) & 0xF) - (int)((z >> shifts[2 * j]) & 0xF);
        int i1 = (int)((q >> shifts[2 * j + 1]) & 0xF) - (int)((z >> shifts[2 * j + 1]) & 0xF);
        out[j] = __floats2half2_rn((float)i0 * sf[2 * j], (float)i1 * sf[2 * j + 1]);
    }
    *reinterpret_cast<uint4*>(&g_W[(size_t)k * N_DIM + (size_t)c * 8]) =
        *reinterpret_cast<const uint4*>(out);
}

// ---------------------------------------------------------------------------
// Kernel 2: pipelined HMMA GEMM (mma.sync m16n8k16, fp32 accum).
// BM=128, BN=128, BK=64, 4-stage cp.async, 8 warps (2x4), warp tile 64x32.
// ---------------------------------------------------------------------------
constexpr int BM = 128, BN = 128, BK = 64;
constexpr int NK = K_DIM / BK;          // 64
constexpr int A_LD = BK + 8;            // 72 halves (144B rows)
constexpr int B_LD = BN + 8;            // 136 halves (272B rows)
constexpr int A_STAGE = BM * A_LD;      // halves
constexpr int B_STAGE = BK * B_LD;      // halves
constexpr int STAGE_H = A_STAGE + B_STAGE;       // halves per stage
constexpr int NSTAGE = 4;
constexpr int GEMM_SMEM = NSTAGE * STAGE_H * 2;  // 143,360 B
constexpr int GROUP_M = 8;              // L2 tile swizzle
constexpr int MT = M_DIM / BM;          // 32
constexpr int NT = N_DIM / BN;          // 86

extern __shared__ __half smem_h[];

__device__ __forceinline__ uint32_t smem_u32(const void* p) {
    uint32_t a;
    asm("{ .reg .u64 t; cvta.to.shared.u64 t, %1; cvt.u32.u64 %0, t; }"
        : "=r"(a) : "l"(p));
    return a;
}
__device__ __forceinline__ void cpa16(uint32_t s, const void* g) {
    asm volatile("cp.async.cg.shared.global [%0], [%1], 16;\n" :: "r"(s), "l"(g));
}
#define CP_COMMIT() asm volatile("cp.async.commit_group;\n" ::: "memory")
#define CP_WAIT(n)  asm volatile("cp.async.wait_group %0;\n" :: "n"(n) : "memory")

__device__ __forceinline__ void ldsm_x4(uint32_t& r0, uint32_t& r1, uint32_t& r2,
                                        uint32_t& r3, uint32_t addr) {
    asm volatile("ldmatrix.sync.aligned.m8n8.x4.shared.b16 {%0,%1,%2,%3}, [%4];"
                 : "=r"(r0), "=r"(r1), "=r"(r2), "=r"(r3) : "r"(addr));
}
__device__ __forceinline__ void ldsm_x4_t(uint32_t& r0, uint32_t& r1, uint32_t& r2,
                                          uint32_t& r3, uint32_t addr) {
    asm volatile("ldmatrix.sync.aligned.m8n8.x4.trans.shared.b16 {%0,%1,%2,%3}, [%4];"
                 : "=r"(r0), "=r"(r1), "=r"(r2), "=r"(r3) : "r"(addr));
}
__device__ __forceinline__ void mma16816(float* c, const uint32_t* a, const uint32_t* b) {
    asm volatile(
        "mma.sync.aligned.m16n8k16.row.col.f32.f16.f16.f32 "
        "{%0,%1,%2,%3}, {%4,%5,%6,%7}, {%8,%9}, {%0,%1,%2,%3};"
        : "+f"(c[0]), "+f"(c[1]), "+f"(c[2]), "+f"(c[3])
        : "r"(a[0]), "r"(a[1]), "r"(a[2]), "r"(a[3]), "r"(b[0]), "r"(b[1]));
}

// stage load: A 128 rows x 64 halves = 1024 16B chunks (4 iters/thread),
//             B 64 rows x 128 halves = 1024 16B chunks (4 iters/thread).
__device__ __forceinline__ void load_stage(uint32_t sb, int tid, int m0, int n0, int kt)
{
    uint32_t a_s = sb;
    uint32_t b_s = sb + A_STAGE * 2;
#pragma unroll
    for (int i = 0; i < 4; ++i) {
        int cid = tid + 256 * i;        // 0..1023
        int row = cid >> 3;             // 0..127
        int kc  = cid & 7;              // 0..7  (16B chunks of 128B row)
        cpa16(a_s + (row * A_LD + kc * 8) * 2,
              g_X + (size_t)(m0 + row) * K_DIM + kt + kc * 8);
    }
#pragma unroll
    for (int i = 0; i < 4; ++i) {
        int cid = tid + 256 * i;        // 0..1023
        int row = cid >> 4;             // 0..63
        int nc  = cid & 15;             // 0..15
        cpa16(b_s + (row * B_LD + nc * 8) * 2,
              g_W + (size_t)(kt + row) * N_DIM + n0 + nc * 8);
    }
}

__global__ void __launch_bounds__(256, 1) gemm_kernel(
    const float* __restrict__ bias,
    float* __restrict__ out)
{
    const int tid  = threadIdx.x;
    const int warp = tid >> 5;
    const int lane = tid & 31;
    const int wm = warp >> 2;           // 0..1 -> 64-row slab
    const int wn = warp & 3;            // 0..3 -> 32-col slab

    // L2-friendly tile order: groups of GROUP_M m-tiles sweep all n-tiles
    int bid = blockIdx.x;
    int grp = bid / (GROUP_M * NT);
    int rem = bid - grp * (GROUP_M * NT);
    int mt  = grp * GROUP_M + rem % GROUP_M;
    int nt  = rem / GROUP_M;
    const int m0 = mt * BM;
    const int n0 = nt * BN;

    const uint32_t sb = smem_u32(smem_h);

    float c[4][4][4];
#pragma unroll
    for (int i = 0; i < 4; ++i)
#pragma unroll
        for (int j = 0; j < 4; ++j)
#pragma unroll
            for (int e = 0; e < 4; ++e) c[i][j][e] = 0.0f;

    // Prologue: stages 0..2
#pragma unroll
    for (int s = 0; s < NSTAGE - 1; ++s) {
        load_stage(sb + s * STAGE_H * 2, tid, m0, n0, s * BK);
        CP_COMMIT();
    }

    const int a_row = lane & 15;          // 0..15
    const int a_c8  = (lane >> 4) * 8;    // 0 or 8
    const int b_row = lane & 15;
    const int b_c8  = (lane >> 4) * 8;

    for (int it = 0; it < NK; ++it) {
        CP_WAIT(2);
        __syncthreads();

        int nxt = it + NSTAGE - 1;
        if (nxt < NK)
            load_stage(sb + (nxt % NSTAGE) * STAGE_H * 2, tid, m0, n0, nxt * BK);
        CP_COMMIT();

        const uint32_t a_s = sb + (it % NSTAGE) * STAGE_H * 2;
        const uint32_t b_s = a_s + A_STAGE * 2;

#pragma unroll
        for (int ks = 0; ks < BK / 16; ++ks) {
            uint32_t af[4][4];
#pragma unroll
            for (int mf = 0; mf < 4; ++mf)
                ldsm_x4(af[mf][0], af[mf][1], af[mf][2], af[mf][3],
                        a_s + ((wm * 64 + mf * 16 + a_row) * A_LD + ks * 16 + a_c8) * 2);
            uint32_t bf[2][4];
#pragma unroll
            for (int nb = 0; nb < 2; ++nb)
                ldsm_x4_t(bf[nb][0], bf[nb][1], bf[nb][2], bf[nb][3],
                          b_s + ((ks * 16 + b_row) * B_LD + wn * 32 + nb * 16 + b_c8) * 2);
#pragma unroll
            for (int mf = 0; mf < 4; ++mf) {
#pragma unroll
                for (int nf = 0; nf < 4; ++nf) {
                    const uint32_t* bp = &bf[nf >> 1][(nf & 1) * 2];
                    mma16816(c[mf][nf], af[mf], bp);
                }
            }
        }
    }

    // -------- epilogue: fp16 round + fp16 bias, f32 stores ----------
    const int qr = lane >> 2;            // 0..7
    const int qc = (lane & 3) * 2;       // 0,2,4,6
#pragma unroll
    for (int nf = 0; nf < 4; ++nf) {
        int col = n0 + wn * 32 + nf * 8 + qc;
        float2 bv = *reinterpret_cast<const float2*>(bias + col);
        __half bh0 = __float2half(bv.x), bh1 = __float2half(bv.y);
#pragma unroll
        for (int mf = 0; mf < 4; ++mf) {
            int row = m0 + wm * 64 + mf * 16 + qr;
            float2 o0, o1;
            o0.x = __half2float(__hadd(__float2half(c[mf][nf][0]), bh0));
            o0.y = __half2float(__hadd(__float2half(c[mf][nf][1]), bh1));
            o1.x = __half2float(__hadd(__float2half(c[mf][nf][2]), bh0));
            o1.y = __half2float(__hadd(__float2half(c[mf][nf][3]), bh1));
            *reinterpret_cast<float2*>(&out[(size_t)row * N_DIM + col]) = o0;
            *reinterpret_cast<float2*>(&out[(size_t)(row + 8) * N_DIM + col]) = o1;
        }
    }
}

// ---------------------------------------------------------------------------
extern "C" void kernel_launch(void* const* d_in, const int* in_sizes, int n_in,
                              void* d_out, int out_size)
{
    const float* x      = (const float*)d_in[0];
    const int*   qw     = (const int*)d_in[1];
    const int*   qz     = (const int*)d_in[2];
    const float* scales = (const float*)d_in[3];
    const float* bias   = (const float*)d_in[4];
    float*       out    = (float*)d_out;

    cudaFuncSetAttribute(gemm_kernel, cudaFuncAttributeMaxDynamicSharedMemorySize,
                         GEMM_SMEM);

    convert_x_kernel<<<(M_DIM * (size_t)K_DIM) / 8 / 256, 256>>>(x);
    dequant_kernel<<<(K_DIM * NPACK + 255) / 256, 256>>>(qw, qz, scales);

    gemm_kernel<<<MT * NT, 256, GEMM_SMEM>>>(bias, out);
}

// round 6
// speedup vs baseline: 1.3271x; 1.0654x over previous
#include <cuda_runtime.h>
#include <cuda_fp16.h>
#include <cstdint>

#define M_DIM 4096
#define K_DIM 4096
#define N_DIM 11008
#define NPACK (N_DIM / 8)   // 1376
#define GROUP 128

// Static scratch: W [K, N] fp16 (90.2 MB) + X [M, K] fp16 (32 MB).
__device__ __half g_W[(size_t)K_DIM * N_DIM];
__device__ __half g_X[(size_t)M_DIM * K_DIM];

// ---------------------------------------------------------------------------
// Kernel 0: x f32 -> fp16 (harness promotes fp16 inputs to f32)
// ---------------------------------------------------------------------------
__global__ void __launch_bounds__(256) convert_x_kernel(const float* __restrict__ x)
{
    size_t i = ((size_t)blockIdx.x * 256 + threadIdx.x) * 8;
    float4 v0 = *reinterpret_cast<const float4*>(x + i);
    float4 v1 = *reinterpret_cast<const float4*>(x + i + 4);
    __half2 o[4];
    o[0] = __floats2half2_rn(v0.x, v0.y);
    o[1] = __floats2half2_rn(v0.z, v0.w);
    o[2] = __floats2half2_rn(v1.x, v1.y);
    o[3] = __floats2half2_rn(v1.z, v1.w);
    *reinterpret_cast<uint4*>(&g_X[i]) = *reinterpret_cast<const uint4*>(o);
}

// ---------------------------------------------------------------------------
// Kernel 1: AWQ int4 dequant -> W [K, N] fp16. One thread per packed word.
// AWQ order map [0,2,4,6,1,3,5,7] -> shifts {0,16,4,20,8,24,12,28}.
// ---------------------------------------------------------------------------
__global__ void __launch_bounds__(256) dequant_kernel(
    const int* __restrict__ qweight,
    const int* __restrict__ qzeros,
    const float* __restrict__ scales)
{
    int idx = blockIdx.x * 256 + threadIdx.x;
    if (idx >= K_DIM * NPACK) return;
    int k = idx / NPACK;
    int c = idx - k * NPACK;
    int g = k >> 7;

    unsigned q = (unsigned)qweight[idx];
    unsigned z = (unsigned)qzeros[g * NPACK + c];

    float4 s0 = *reinterpret_cast<const float4*>(scales + (size_t)g * N_DIM + (size_t)c * 8);
    float4 s1 = *reinterpret_cast<const float4*>(scales + (size_t)g * N_DIM + (size_t)c * 8 + 4);
    float sf[8] = {s0.x, s0.y, s0.z, s0.w, s1.x, s1.y, s1.z, s1.w};

    const int shifts[8] = {0, 16, 4, 20, 8, 24, 12, 28};
    __half2 out[4];
#pragma unroll
    for (int j = 0; j < 4; ++j) {
        int i0 = (int)((q >> shifts[2 * j]) & 0xF) - (int)((z >> shifts[2 * j]) & 0xF);
        int i1 = (int)((q >> shifts[2 * j + 1]) & 0xF) - (int)((z >> shifts[2 * j + 1]) & 0xF);
        out[j] = __floats2half2_rn((float)i0 * sf[2 * j], (float)i1 * sf[2 * j + 1]);
    }
    *reinterpret_cast<uint4*>(&g_W[(size_t)k * N_DIM + (size_t)c * 8]) =
        *reinterpret_cast<const uint4*>(out);
}

// ---------------------------------------------------------------------------
// Kernel 2: pipelined HMMA GEMM (mma.sync m16n8k16, fp32 accum).
// CTA tile 128(M) x 256(N), BK=64, 3-stage cp.async, 8 warps (2x4),
// warp tile 64x64 -> 2x fewer smem reads per MAC than 64x32.
// ---------------------------------------------------------------------------
constexpr int BM = 128, BN = 256, BK = 64;
constexpr int NK = K_DIM / BK;          // 64
constexpr int A_LD = BK + 8;            // 72 halves (144B rows)
constexpr int B_LD = BN + 8;            // 264 halves (528B rows)
constexpr int A_STAGE = BM * A_LD;      // 9216 halves
constexpr int B_STAGE = BK * B_LD;      // 16896 halves
constexpr int STAGE_H = A_STAGE + B_STAGE;       // 26112 halves
constexpr int NSTAGE = 3;
constexpr int GEMM_SMEM = NSTAGE * STAGE_H * 2;  // 156,672 B
constexpr int GROUP_M = 8;
constexpr int MT = M_DIM / BM;          // 32
constexpr int NT = N_DIM / BN;          // 43

extern __shared__ __half smem_h[];

__device__ __forceinline__ uint32_t smem_u32(const void* p) {
    uint32_t a;
    asm("{ .reg .u64 t; cvta.to.shared.u64 t, %1; cvt.u32.u64 %0, t; }"
        : "=r"(a) : "l"(p));
    return a;
}
__device__ __forceinline__ void cpa16(uint32_t s, const void* g) {
    asm volatile("cp.async.cg.shared.global [%0], [%1], 16;\n" :: "r"(s), "l"(g));
}
#define CP_COMMIT() asm volatile("cp.async.commit_group;\n" ::: "memory")
#define CP_WAIT(n)  asm volatile("cp.async.wait_group %0;\n" :: "n"(n) : "memory")

__device__ __forceinline__ void ldsm_x4(uint32_t& r0, uint32_t& r1, uint32_t& r2,
                                        uint32_t& r3, uint32_t addr) {
    asm volatile("ldmatrix.sync.aligned.m8n8.x4.shared.b16 {%0,%1,%2,%3}, [%4];"
                 : "=r"(r0), "=r"(r1), "=r"(r2), "=r"(r3) : "r"(addr));
}
__device__ __forceinline__ void ldsm_x4_t(uint32_t& r0, uint32_t& r1, uint32_t& r2,
                                          uint32_t& r3, uint32_t addr) {
    asm volatile("ldmatrix.sync.aligned.m8n8.x4.trans.shared.b16 {%0,%1,%2,%3}, [%4];"
                 : "=r"(r0), "=r"(r1), "=r"(r2), "=r"(r3) : "r"(addr));
}
__device__ __forceinline__ void mma16816(float* c, const uint32_t* a, const uint32_t* b) {
    asm volatile(
        "mma.sync.aligned.m16n8k16.row.col.f32.f16.f16.f32 "
        "{%0,%1,%2,%3}, {%4,%5,%6,%7}, {%8,%9}, {%0,%1,%2,%3};"
        : "+f"(c[0]), "+f"(c[1]), "+f"(c[2]), "+f"(c[3])
        : "r"(a[0]), "r"(a[1]), "r"(a[2]), "r"(a[3]), "r"(b[0]), "r"(b[1]));
}

// stage load: A 128 rows x 64 halves = 1024 16B chunks (4 iters),
//             B 64 rows x 256 halves = 2048 16B chunks (8 iters).
__device__ __forceinline__ void load_stage(uint32_t sb, int tid, int m0, int n0, int kt)
{
    uint32_t a_s = sb;
    uint32_t b_s = sb + A_STAGE * 2;
#pragma unroll
    for (int i = 0; i < 4; ++i) {
        int cid = tid + 256 * i;        // 0..1023
        int row = cid >> 3;             // 0..127
        int kc  = cid & 7;              // 0..7
        cpa16(a_s + (row * A_LD + kc * 8) * 2,
              g_X + (size_t)(m0 + row) * K_DIM + kt + kc * 8);
    }
#pragma unroll
    for (int i = 0; i < 8; ++i) {
        int cid = tid + 256 * i;        // 0..2047
        int row = cid >> 5;             // 0..63
        int nc  = cid & 31;             // 0..31
        cpa16(b_s + (row * B_LD + nc * 8) * 2,
              g_W + (size_t)(kt + row) * N_DIM + n0 + nc * 8);
    }
}

__global__ void __launch_bounds__(256, 1) gemm_kernel(
    const float* __restrict__ bias,
    float* __restrict__ out)
{
    const int tid  = threadIdx.x;
    const int warp = tid >> 5;
    const int lane = tid & 31;
    const int wm = warp >> 2;           // 0..1 -> 64-row slab
    const int wn = warp & 3;            // 0..3 -> 64-col slab

    int bid = blockIdx.x;
    int grp = bid / (GROUP_M * NT);
    int rem = bid - grp * (GROUP_M * NT);
    int mt  = grp * GROUP_M + rem % GROUP_M;
    int nt  = rem / GROUP_M;
    const int m0 = mt * BM;
    const int n0 = nt * BN;

    const uint32_t sb = smem_u32(smem_h);

    float c[4][8][4];
#pragma unroll
    for (int i = 0; i < 4; ++i)
#pragma unroll
        for (int j = 0; j < 8; ++j)
#pragma unroll
            for (int e = 0; e < 4; ++e) c[i][j][e] = 0.0f;

    // Prologue: stages 0, 1
#pragma unroll
    for (int s = 0; s < NSTAGE - 1; ++s) {
        load_stage(sb + s * STAGE_H * 2, tid, m0, n0, s * BK);
        CP_COMMIT();
    }

    const int a_row = lane & 15;
    const int a_c8  = (lane >> 4) * 8;
    const int b_row = lane & 15;
    const int b_c8  = (lane >> 4) * 8;

    for (int it = 0; it < NK; ++it) {
        CP_WAIT(1);            // stage `it` resident (see group accounting)
        __syncthreads();

        int nxt = it + NSTAGE - 1;
        if (nxt < NK)
            load_stage(sb + (nxt % NSTAGE) * STAGE_H * 2, tid, m0, n0, nxt * BK);
        CP_COMMIT();

        const uint32_t a_s = sb + (it % NSTAGE) * STAGE_H * 2;
        const uint32_t b_s = a_s + A_STAGE * 2;

#pragma unroll
        for (int ks = 0; ks < BK / 16; ++ks) {
            uint32_t af[4][4];
#pragma unroll
            for (int mf = 0; mf < 4; ++mf)
                ldsm_x4(af[mf][0], af[mf][1], af[mf][2], af[mf][3],
                        a_s + ((wm * 64 + mf * 16 + a_row) * A_LD + ks * 16 + a_c8) * 2);
            uint32_t bf[4][4];
#pragma unroll
            for (int nb = 0; nb < 4; ++nb)
                ldsm_x4_t(bf[nb][0], bf[nb][1], bf[nb][2], bf[nb][3],
                          b_s + ((ks * 16 + b_row) * B_LD + wn * 64 + nb * 16 + b_c8) * 2);
#pragma unroll
            for (int mf = 0; mf < 4; ++mf) {
#pragma unroll
                for (int nf = 0; nf < 8; ++nf) {
                    const uint32_t* bp = &bf[nf >> 1][(nf & 1) * 2];
                    mma16816(c[mf][nf], af[mf], bp);
                }
            }
        }
    }

    // -------- epilogue: fp16 round + fp16 bias, f32 stores ----------
    const int qr = lane >> 2;            // 0..7
    const int qc = (lane & 3) * 2;       // 0,2,4,6
#pragma unroll
    for (int nf = 0; nf < 8; ++nf) {
        int col = n0 + wn * 64 + nf * 8 + qc;
        float2 bv = *reinterpret_cast<const float2*>(bias + col);
        __half bh0 = __float2half(bv.x), bh1 = __float2half(bv.y);
#pragma unroll
        for (int mf = 0; mf < 4; ++mf) {
            int row = m0 + wm * 64 + mf * 16 + qr;
            float2 o0, o1;
            o0.x = __half2float(__hadd(__float2half(c[mf][nf][0]), bh0));
            o0.y = __half2float(__hadd(__float2half(c[mf][nf][1]), bh1));
            o1.x = __half2float(__hadd(__float2half(c[mf][nf][2]), bh0));
            o1.y = __half2float(__hadd(__float2half(c[mf][nf][3]), bh1));
            *reinterpret_cast<float2*>(&out[(size_t)row * N_DIM + col]) = o0;
            *reinterpret_cast<float2*>(&out[(size_t)(row + 8) * N_DIM + col]) = o1;
        }
    }
}

// ---------------------------------------------------------------------------
extern "C" void kernel_launch(void* const* d_in, const int* in_sizes, int n_in,
                              void* d_out, int out_size)
{
    const float* x      = (const float*)d_in[0];
    const int*   qw     = (const int*)d_in[1];
    const int*   qz     = (const int*)d_in[2];
    const float* scales = (const float*)d_in[3];
    const float* bias   = (const float*)d_in[4];
    float*       out    = (float*)d_out;

    cudaFuncSetAttribute(gemm_kernel, cudaFuncAttributeMaxDynamicSharedMemorySize,
                         GEMM_SMEM);

    convert_x_kernel<<<(M_DIM * (size_t)K_DIM) / 8 / 256, 256>>>(x);
    dequant_kernel<<<(K_DIM * NPACK + 255) / 256, 256>>>(qw, qz, scales);

    gemm_kernel<<<MT * NT, 256, GEMM_SMEM>>>(bias, out);
}

// round 7
// speedup vs baseline: 1.5963x; 1.2028x over previous
#include <cuda_runtime.h>
#include <cuda_fp16.h>
#include <cstdint>

#define M_DIM 4096
#define K_DIM 4096
#define N_DIM 11008
#define NPACK (N_DIM / 8)   // 1376
#define GROUP 128

// Static scratch: W [K, N] fp16 (90.2 MB) + X [M, K] fp16 (32 MB).
__device__ __half g_W[(size_t)K_DIM * N_DIM];
__device__ __half g_X[(size_t)M_DIM * K_DIM];

// ---------------------------------------------------------------------------
// Kernel 0: x f32 -> fp16 (harness promotes fp16 inputs to f32)
// ---------------------------------------------------------------------------
__global__ void __launch_bounds__(256) convert_x_kernel(const float* __restrict__ x)
{
    size_t i = ((size_t)blockIdx.x * 256 + threadIdx.x) * 8;
    float4 v0 = *reinterpret_cast<const float4*>(x + i);
    float4 v1 = *reinterpret_cast<const float4*>(x + i + 4);
    __half2 o[4];
    o[0] = __floats2half2_rn(v0.x, v0.y);
    o[1] = __floats2half2_rn(v0.z, v0.w);
    o[2] = __floats2half2_rn(v1.x, v1.y);
    o[3] = __floats2half2_rn(v1.z, v1.w);
    *reinterpret_cast<uint4*>(&g_X[i]) = *reinterpret_cast<const uint4*>(o);
}

// ---------------------------------------------------------------------------
// Kernel 1: AWQ int4 dequant -> W [K, N] fp16. One thread per packed word.
// AWQ order map [0,2,4,6,1,3,5,7] -> shifts {0,16,4,20,8,24,12,28}.
// ---------------------------------------------------------------------------
__global__ void __launch_bounds__(256) dequant_kernel(
    const int* __restrict__ qweight,
    const int* __restrict__ qzeros,
    const float* __restrict__ scales)
{
    int idx = blockIdx.x * 256 + threadIdx.x;
    if (idx >= K_DIM * NPACK) return;
    int k = idx / NPACK;
    int c = idx - k * NPACK;
    int g = k >> 7;

    unsigned q = (unsigned)qweight[idx];
    unsigned z = (unsigned)qzeros[g * NPACK + c];

    float4 s0 = *reinterpret_cast<const float4*>(scales + (size_t)g * N_DIM + (size_t)c * 8);
    float4 s1 = *reinterpret_cast<const float4*>(scales + (size_t)g * N_DIM + (size_t)c * 8 + 4);
    float sf[8] = {s0.x, s0.y, s0.z, s0.w, s1.x, s1.y, s1.z, s1.w};

    const int shifts[8] = {0, 16, 4, 20, 8, 24, 12, 28};
    __half2 out[4];
#pragma unroll
    for (int j = 0; j < 4; ++j) {
        int i0 = (int)((q >> shifts[2 * j]) & 0xF) - (int)((z >> shifts[2 * j]) & 0xF);
        int i1 = (int)((q >> shifts[2 * j + 1]) & 0xF) - (int)((z >> shifts[2 * j + 1]) & 0xF);
        out[j] = __floats2half2_rn((float)i0 * sf[2 * j], (float)i1 * sf[2 * j + 1]);
    }
    *reinterpret_cast<uint4*>(&g_W[(size_t)k * N_DIM + (size_t)c * 8]) =
        *reinterpret_cast<const uint4*>(out);
}

// ---------------------------------------------------------------------------
// Kernel 2: pipelined HMMA GEMM (mma.sync m16n8k16, fp32 accum).
// CTA tile 128x128, BK=64, 3-stage cp.async, 4 warps (2x2), warp tile 64x64.
// 107.5 KB smem/CTA -> 2 CTAs/SM to hide sync/load bubbles.
// ---------------------------------------------------------------------------
constexpr int BM = 128, BN = 128, BK = 64;
constexpr int NK = K_DIM / BK;          // 64
constexpr int A_LD = BK + 8;            // 72 halves (144B rows)
constexpr int B_LD = BN + 8;            // 136 halves (272B rows)
constexpr int A_STAGE = BM * A_LD;      // 9216 halves
constexpr int B_STAGE = BK * B_LD;      // 8704 halves
constexpr int STAGE_H = A_STAGE + B_STAGE;       // 17920 halves
constexpr int NSTAGE = 3;
constexpr int GEMM_SMEM = NSTAGE * STAGE_H * 2;  // 107,520 B
constexpr int NTHREADS = 128;
constexpr int GROUP_M = 8;
constexpr int MT = M_DIM / BM;          // 32
constexpr int NT = N_DIM / BN;          // 86

extern __shared__ __half smem_h[];

__device__ __forceinline__ uint32_t smem_u32(const void* p) {
    uint32_t a;
    asm("{ .reg .u64 t; cvta.to.shared.u64 t, %1; cvt.u32.u64 %0, t; }"
        : "=r"(a) : "l"(p));
    return a;
}
__device__ __forceinline__ void cpa16(uint32_t s, const void* g) {
    asm volatile("cp.async.cg.shared.global [%0], [%1], 16;\n" :: "r"(s), "l"(g));
}
#define CP_COMMIT() asm volatile("cp.async.commit_group;\n" ::: "memory")
#define CP_WAIT(n)  asm volatile("cp.async.wait_group %0;\n" :: "n"(n) : "memory")

__device__ __forceinline__ void ldsm_x4(uint32_t& r0, uint32_t& r1, uint32_t& r2,
                                        uint32_t& r3, uint32_t addr) {
    asm volatile("ldmatrix.sync.aligned.m8n8.x4.shared.b16 {%0,%1,%2,%3}, [%4];"
                 : "=r"(r0), "=r"(r1), "=r"(r2), "=r"(r3) : "r"(addr));
}
__device__ __forceinline__ void ldsm_x4_t(uint32_t& r0, uint32_t& r1, uint32_t& r2,
                                          uint32_t& r3, uint32_t addr) {
    asm volatile("ldmatrix.sync.aligned.m8n8.x4.trans.shared.b16 {%0,%1,%2,%3}, [%4];"
                 : "=r"(r0), "=r"(r1), "=r"(r2), "=r"(r3) : "r"(addr));
}
__device__ __forceinline__ void mma16816(float* c, const uint32_t* a, const uint32_t* b) {
    asm volatile(
        "mma.sync.aligned.m16n8k16.row.col.f32.f16.f16.f32 "
        "{%0,%1,%2,%3}, {%4,%5,%6,%7}, {%8,%9}, {%0,%1,%2,%3};"
        : "+f"(c[0]), "+f"(c[1]), "+f"(c[2]), "+f"(c[3])
        : "r"(a[0]), "r"(a[1]), "r"(a[2]), "r"(a[3]), "r"(b[0]), "r"(b[1]));
}

// stage load (128 threads): A 128x64 halves = 1024 chunks (8 iters),
//                           B 64x128 halves = 1024 chunks (8 iters).
__device__ __forceinline__ void load_stage(uint32_t sb, int tid, int m0, int n0, int kt)
{
    uint32_t a_s = sb;
    uint32_t b_s = sb + A_STAGE * 2;
#pragma unroll
    for (int i = 0; i < 8; ++i) {
        int cid = tid + NTHREADS * i;   // 0..1023
        int row = cid >> 3;             // 0..127
        int kc  = cid & 7;              // 0..7
        cpa16(a_s + (row * A_LD + kc * 8) * 2,
              g_X + (size_t)(m0 + row) * K_DIM + kt + kc * 8);
    }
#pragma unroll
    for (int i = 0; i < 8; ++i) {
        int cid = tid + NTHREADS * i;   // 0..1023
        int row = cid >> 4;             // 0..63
        int nc  = cid & 15;             // 0..15
        cpa16(b_s + (row * B_LD + nc * 8) * 2,
              g_W + (size_t)(kt + row) * N_DIM + n0 + nc * 8);
    }
}

__global__ void __launch_bounds__(NTHREADS, 2) gemm_kernel(
    const float* __restrict__ bias,
    float* __restrict__ out)
{
    const int tid  = threadIdx.x;
    const int warp = tid >> 5;
    const int lane = tid & 31;
    const int wm = warp >> 1;           // 0..1 -> 64-row slab
    const int wn = warp & 1;            // 0..1 -> 64-col slab

    int bid = blockIdx.x;
    int grp = bid / (GROUP_M * NT);
    int rem = bid - grp * (GROUP_M * NT);
    int mt  = grp * GROUP_M + rem % GROUP_M;
    int nt  = rem / GROUP_M;
    const int m0 = mt * BM;
    const int n0 = nt * BN;

    const uint32_t sb = smem_u32(smem_h);

    float c[4][8][4];
#pragma unroll
    for (int i = 0; i < 4; ++i)
#pragma unroll
        for (int j = 0; j < 8; ++j)
#pragma unroll
            for (int e = 0; e < 4; ++e) c[i][j][e] = 0.0f;

    // Prologue: stages 0, 1
#pragma unroll
    for (int s = 0; s < NSTAGE - 1; ++s) {
        load_stage(sb + s * STAGE_H * 2, tid, m0, n0, s * BK);
        CP_COMMIT();
    }

    const int a_row = lane & 15;
    const int a_c8  = (lane >> 4) * 8;
    const int b_row = lane & 15;
    const int b_c8  = (lane >> 4) * 8;

    for (int it = 0; it < NK; ++it) {
        CP_WAIT(1);            // stage `it` resident
        __syncthreads();

        int nxt = it + NSTAGE - 1;
        if (nxt < NK)
            load_stage(sb + (nxt % NSTAGE) * STAGE_H * 2, tid, m0, n0, nxt * BK);
        CP_COMMIT();

        const uint32_t a_s = sb + (it % NSTAGE) * STAGE_H * 2;
        const uint32_t b_s = a_s + A_STAGE * 2;

#pragma unroll
        for (int ks = 0; ks < BK / 16; ++ks) {
            uint32_t af[4][4];
#pragma unroll
            for (int mf = 0; mf < 4; ++mf)
                ldsm_x4(af[mf][0], af[mf][1], af[mf][2], af[mf][3],
                        a_s + ((wm * 64 + mf * 16 + a_row) * A_LD + ks * 16 + a_c8) * 2);
            uint32_t bf[4][4];
#pragma unroll
            for (int nb = 0; nb < 4; ++nb)
                ldsm_x4_t(bf[nb][0], bf[nb][1], bf[nb][2], bf[nb][3],
                          b_s + ((ks * 16 + b_row) * B_LD + wn * 64 + nb * 16 + b_c8) * 2);
#pragma unroll
            for (int mf = 0; mf < 4; ++mf) {
#pragma unroll
                for (int nf = 0; nf < 8; ++nf) {
                    const uint32_t* bp = &bf[nf >> 1][(nf & 1) * 2];
                    mma16816(c[mf][nf], af[mf], bp);
                }
            }
        }
    }

    // -------- epilogue: fp16 round + fp16 bias, f32 stores ----------
    const int qr = lane >> 2;            // 0..7
    const int qc = (lane & 3) * 2;       // 0,2,4,6
#pragma unroll
    for (int nf = 0; nf < 8; ++nf) {
        int col = n0 + wn * 64 + nf * 8 + qc;
        float2 bv = *reinterpret_cast<const float2*>(bias + col);
        __half bh0 = __float2half(bv.x), bh1 = __float2half(bv.y);
#pragma unroll
        for (int mf = 0; mf < 4; ++mf) {
            int row = m0 + wm * 64 + mf * 16 + qr;
            float2 o0, o1;
            o0.x = __half2float(__hadd(__float2half(c[mf][nf][0]), bh0));
            o0.y = __half2float(__hadd(__float2half(c[mf][nf][1]), bh1));
            o1.x = __half2float(__hadd(__float2half(c[mf][nf][2]), bh0));
            o1.y = __half2float(__hadd(__float2half(c[mf][nf][3]), bh1));
            *reinterpret_cast<float2*>(&out[(size_t)row * N_DIM + col]) = o0;
            *reinterpret_cast<float2*>(&out[(size_t)(row + 8) * N_DIM + col]) = o1;
        }
    }
}

// ---------------------------------------------------------------------------
extern "C" void kernel_launch(void* const* d_in, const int* in_sizes, int n_in,
                              void* d_out, int out_size)
{
    const float* x      = (const float*)d_in[0];
    const int*   qw     = (const int*)d_in[1];
    const int*   qz     = (const int*)d_in[2];
    const float* scales = (const float*)d_in[3];
    const float* bias   = (const float*)d_in[4];
    float*       out    = (float*)d_out;

    cudaFuncSetAttribute(gemm_kernel, cudaFuncAttributeMaxDynamicSharedMemorySize,
                         GEMM_SMEM);

    convert_x_kernel<<<(M_DIM * (size_t)K_DIM) / 8 / 256, 256>>>(x);
    dequant_kernel<<<(K_DIM * NPACK + 255) / 256, 256>>>(qw, qz, scales);

    gemm_kernel<<<MT * NT, NTHREADS, GEMM_SMEM>>>(bias, out);
}